// round 1
// baseline (speedup 1.0000x reference)
#include <cuda_runtime.h>
#include <cuda_bf16.h>
#include <math.h>

// Problem constants
#define BATCH  8
#define T_DIM  1024
#define I_DIM  576
#define C_DIM  1024
#define N_HEAD 16
#define HD     64

// ---------------------------------------------------------------------------
// Scratch (device globals; no allocation allowed)
// ---------------------------------------------------------------------------
__device__ float g_q [BATCH * T_DIM * C_DIM];        // 33.5 MB
__device__ float g_kv[BATCH * I_DIM * 2 * C_DIM];    // 37.7 MB
__device__ float g_y [BATCH * T_DIM * C_DIM];        // 33.5 MB

// ---------------------------------------------------------------------------
// SGEMM NT: C[M,N] = A[M,K] * B[N,K]^T + bias[N]
// 128x128x16 tile, 256 threads, 8x8 micro-tile
// ---------------------------------------------------------------------------
#define GBM 128
#define GBN 128
#define GBK 16

__global__ __launch_bounds__(256) void sgemm_nt(
    const float* __restrict__ A, const float* __restrict__ B,
    const float* __restrict__ bias, float* __restrict__ C,
    int M, int N, int K)
{
    __shared__ float As[GBK][GBM + 4];
    __shared__ float Bs[GBK][GBN + 4];

    const int tid = threadIdx.x;
    const int m0  = blockIdx.y * GBM;
    const int n0  = blockIdx.x * GBN;

    // loader mapping: 64 rows x 16 k covered by 256 threads (float4 each), two row passes
    const int lr = tid >> 2;          // 0..63
    const int lc = (tid & 3) << 2;    // 0,4,8,12

    const float* Ag = A + (size_t)(m0 + lr) * K + lc;
    const float* Bg = B + (size_t)(n0 + lr) * K + lc;

    const int ty = tid >> 4;          // 0..15
    const int tx = tid & 15;          // 0..15

    float acc[8][8];
#pragma unroll
    for (int i = 0; i < 8; i++)
#pragma unroll
        for (int j = 0; j < 8; j++) acc[i][j] = 0.f;

    for (int k0 = 0; k0 < K; k0 += GBK) {
        float4 a0 = *(const float4*)(Ag + k0);
        float4 a1 = *(const float4*)(Ag + (size_t)64 * K + k0);
        float4 b0 = *(const float4*)(Bg + k0);
        float4 b1 = *(const float4*)(Bg + (size_t)64 * K + k0);

        __syncthreads();   // previous iteration's compute done with smem

        As[lc + 0][lr] = a0.x; As[lc + 1][lr] = a0.y;
        As[lc + 2][lr] = a0.z; As[lc + 3][lr] = a0.w;
        As[lc + 0][lr + 64] = a1.x; As[lc + 1][lr + 64] = a1.y;
        As[lc + 2][lr + 64] = a1.z; As[lc + 3][lr + 64] = a1.w;

        Bs[lc + 0][lr] = b0.x; Bs[lc + 1][lr] = b0.y;
        Bs[lc + 2][lr] = b0.z; Bs[lc + 3][lr] = b0.w;
        Bs[lc + 0][lr + 64] = b1.x; Bs[lc + 1][lr + 64] = b1.y;
        Bs[lc + 2][lr + 64] = b1.z; Bs[lc + 3][lr + 64] = b1.w;

        __syncthreads();

#pragma unroll
        for (int kk = 0; kk < GBK; kk++) {
            float a[8], b[8];
            *(float4*)(a)     = *(const float4*)&As[kk][ty * 8];
            *(float4*)(a + 4) = *(const float4*)&As[kk][ty * 8 + 4];
            *(float4*)(b)     = *(const float4*)&Bs[kk][tx * 8];
            *(float4*)(b + 4) = *(const float4*)&Bs[kk][tx * 8 + 4];
#pragma unroll
            for (int i = 0; i < 8; i++)
#pragma unroll
                for (int j = 0; j < 8; j++)
                    acc[i][j] += a[i] * b[j];
        }
    }

    // epilogue
    float bv[8];
#pragma unroll
    for (int j = 0; j < 8; j++) bv[j] = bias[n0 + tx * 8 + j];

#pragma unroll
    for (int i = 0; i < 8; i++) {
        float* cp = C + (size_t)(m0 + ty * 8 + i) * N + n0 + tx * 8;
        float4 o0 = make_float4(acc[i][0] + bv[0], acc[i][1] + bv[1],
                                acc[i][2] + bv[2], acc[i][3] + bv[3]);
        float4 o1 = make_float4(acc[i][4] + bv[4], acc[i][5] + bv[5],
                                acc[i][6] + bv[6], acc[i][7] + bv[7]);
        *(float4*)(cp)     = o0;
        *(float4*)(cp + 4) = o1;
    }
}

// ---------------------------------------------------------------------------
// Attention: per (b, h, 32-row t-tile). Full S row in smem, two-pass softmax.
// q: [B,T,C] (head h at col h*64); kv: [B,I,2C] (k at h*64, v at C+h*64)
// y: [B,T,C]
// ---------------------------------------------------------------------------
#define SQ_STRIDE 65
#define SS_STRIDE 577
#define ST_STRIDE 65
#define ATTN_SMEM_FLOATS (32 * SQ_STRIDE + 32 * SS_STRIDE + 64 * ST_STRIDE + 32)
#define ATTN_SMEM_BYTES  (ATTN_SMEM_FLOATS * 4)

__global__ __launch_bounds__(256) void attn_kernel(
    const float* __restrict__ qb, const float* __restrict__ kvb,
    float* __restrict__ yb)
{
    extern __shared__ float sm[];
    float* sQ = sm;                              // [32][65]
    float* sS = sQ + 32 * SQ_STRIDE;             // [32][577]
    float* sT = sS + 32 * SS_STRIDE;             // [64][65]   K/V staging
    float* sL = sT + 64 * ST_STRIDE;             // [32]       row sums

    const int tid = threadIdx.x;
    const int b = blockIdx.z;
    const int h = blockIdx.y;
    const int t0 = blockIdx.x * 32;

    // load Q tile [32][64]
    {
        const float* qptr = qb + ((size_t)b * T_DIM + t0) * C_DIM + h * HD;
        for (int idx = tid; idx < 32 * 64; idx += 256) {
            int t = idx >> 6, d = idx & 63;
            sQ[t * SQ_STRIDE + d] = qptr[(size_t)t * C_DIM + d];
        }
    }
    __syncthreads();

    const int tt   = tid >> 4;      // 0..15 -> rows 2*tt, 2*tt+1
    const int ii   = tid & 15;      // 0..15 -> cols 4*ii..4*ii+3
    const int trow = tt * 2;
    const int icol = ii * 4;

    // ----- Phase 1: S = (Q K^T) * 1/sqrt(64) -----
    for (int i0 = 0; i0 < I_DIM; i0 += 64) {
        const float* kptr = kvb + ((size_t)b * I_DIM + i0) * (2 * C_DIM) + h * HD;
        for (int idx = tid; idx < 64 * 64; idx += 256) {
            int i = idx >> 6, d = idx & 63;
            sT[i * ST_STRIDE + d] = kptr[(size_t)i * (2 * C_DIM) + d];
        }
        __syncthreads();

        float a00 = 0.f, a01 = 0.f, a02 = 0.f, a03 = 0.f;
        float a10 = 0.f, a11 = 0.f, a12 = 0.f, a13 = 0.f;
        const float* q0p = &sQ[trow * SQ_STRIDE];
        const float* q1p = &sQ[(trow + 1) * SQ_STRIDE];
        const float* k0p = &sT[(icol + 0) * ST_STRIDE];
        const float* k1p = &sT[(icol + 1) * ST_STRIDE];
        const float* k2p = &sT[(icol + 2) * ST_STRIDE];
        const float* k3p = &sT[(icol + 3) * ST_STRIDE];
#pragma unroll 16
        for (int d = 0; d < 64; d++) {
            float q0 = q0p[d], q1 = q1p[d];
            float k0 = k0p[d], k1 = k1p[d], k2 = k2p[d], k3 = k3p[d];
            a00 += q0 * k0; a01 += q0 * k1; a02 += q0 * k2; a03 += q0 * k3;
            a10 += q1 * k0; a11 += q1 * k1; a12 += q1 * k2; a13 += q1 * k3;
        }
        float* s0 = &sS[trow * SS_STRIDE + i0 + icol];
        float* s1 = &sS[(trow + 1) * SS_STRIDE + i0 + icol];
        s0[0] = a00 * 0.125f; s0[1] = a01 * 0.125f; s0[2] = a02 * 0.125f; s0[3] = a03 * 0.125f;
        s1[0] = a10 * 0.125f; s1[1] = a11 * 0.125f; s1[2] = a12 * 0.125f; s1[3] = a13 * 0.125f;
        __syncthreads();
    }

    // ----- Phase 2: softmax over i (576). 8 threads per row. -----
    {
        const int row = tid >> 3, g = tid & 7;
        float* sr = &sS[row * SS_STRIDE];
        float m = -1e30f;
        for (int i = g; i < I_DIM; i += 8) m = fmaxf(m, sr[i]);
        m = fmaxf(m, __shfl_xor_sync(0xffffffffu, m, 1));
        m = fmaxf(m, __shfl_xor_sync(0xffffffffu, m, 2));
        m = fmaxf(m, __shfl_xor_sync(0xffffffffu, m, 4));
        float s = 0.f;
        for (int i = g; i < I_DIM; i += 8) {
            float e = __expf(sr[i] - m);
            sr[i] = e;
            s += e;
        }
        s += __shfl_xor_sync(0xffffffffu, s, 1);
        s += __shfl_xor_sync(0xffffffffu, s, 2);
        s += __shfl_xor_sync(0xffffffffu, s, 4);
        if (g == 0) sL[row] = s;
    }
    __syncthreads();

    // ----- Phase 3: Y = P V (then divide by row sum) -----
    float y00 = 0.f, y01 = 0.f, y02 = 0.f, y03 = 0.f;
    float y10 = 0.f, y11 = 0.f, y12 = 0.f, y13 = 0.f;
    for (int i0 = 0; i0 < I_DIM; i0 += 64) {
        const float* vptr = kvb + ((size_t)b * I_DIM + i0) * (2 * C_DIM) + C_DIM + h * HD;
        for (int idx = tid; idx < 64 * 64; idx += 256) {
            int i = idx >> 6, d = idx & 63;
            sT[i * ST_STRIDE + d] = vptr[(size_t)i * (2 * C_DIM) + d];
        }
        __syncthreads();

        const float* p0p = &sS[trow * SS_STRIDE + i0];
        const float* p1p = &sS[(trow + 1) * SS_STRIDE + i0];
#pragma unroll 8
        for (int i = 0; i < 64; i++) {
            float p0 = p0p[i], p1 = p1p[i];
            const float* vp = &sT[i * ST_STRIDE + icol];
            float v0 = vp[0], v1 = vp[1], v2 = vp[2], v3 = vp[3];
            y00 += p0 * v0; y01 += p0 * v1; y02 += p0 * v2; y03 += p0 * v3;
            y10 += p1 * v0; y11 += p1 * v1; y12 += p1 * v2; y13 += p1 * v3;
        }
        __syncthreads();
    }

    const float inv0 = 1.0f / sL[trow];
    const float inv1 = 1.0f / sL[trow + 1];
    float* y0p = yb + ((size_t)b * T_DIM + t0 + trow) * C_DIM + h * HD + icol;
    float* y1p = y0p + C_DIM;
    y0p[0] = y00 * inv0; y0p[1] = y01 * inv0; y0p[2] = y02 * inv0; y0p[3] = y03 * inv0;
    y1p[0] = y10 * inv1; y1p[1] = y11 * inv1; y1p[2] = y12 * inv1; y1p[3] = y13 * inv1;
}

// ---------------------------------------------------------------------------
// Launch
// ---------------------------------------------------------------------------
extern "C" void kernel_launch(void* const* d_in, const int* in_sizes, int n_in,
                              void* d_out, int out_size)
{
    const float* x   = (const float*)d_in[0];
    const float* enc = (const float*)d_in[1];
    const float* Wq  = (const float*)d_in[2];
    const float* bq  = (const float*)d_in[3];
    const float* Wkv = (const float*)d_in[4];
    const float* bkv = (const float*)d_in[5];
    const float* Wo  = (const float*)d_in[6];
    const float* bo  = (const float*)d_in[7];
    float* out = (float*)d_out;

    float *qp, *kvp, *yp;
    cudaGetSymbolAddress((void**)&qp,  g_q);
    cudaGetSymbolAddress((void**)&kvp, g_kv);
    cudaGetSymbolAddress((void**)&yp,  g_y);

    cudaFuncSetAttribute(attn_kernel,
                         cudaFuncAttributeMaxDynamicSharedMemorySize,
                         ATTN_SMEM_BYTES);

    // Q = x @ Wq^T + bq           : M=8192, N=1024, K=1024
    sgemm_nt<<<dim3(C_DIM / GBN, (BATCH * T_DIM) / GBM), 256>>>(
        x, Wq, bq, qp, BATCH * T_DIM, C_DIM, C_DIM);

    // KV = enc @ Wkv^T + bkv      : M=4608, N=2048, K=1024
    sgemm_nt<<<dim3((2 * C_DIM) / GBN, (BATCH * I_DIM) / GBM), 256>>>(
        enc, Wkv, bkv, kvp, BATCH * I_DIM, 2 * C_DIM, C_DIM);

    // attention -> y
    attn_kernel<<<dim3(T_DIM / 32, N_HEAD, BATCH), 256, ATTN_SMEM_BYTES>>>(
        qp, kvp, yp);

    // out = y @ Wo^T + bo         : M=8192, N=1024, K=1024
    sgemm_nt<<<dim3(C_DIM / GBN, (BATCH * T_DIM) / GBM), 256>>>(
        yp, Wo, bo, out, BATCH * T_DIM, C_DIM, C_DIM);
}